// round 5
// baseline (speedup 1.0000x reference)
#include <cuda_runtime.h>
#include <math.h>

// Problem constants
#define NV 50000
#define NE 640000
#define NHALF 320000
#define NTILES (NE/64)        // 10000
#define HALF_TILES (NHALF/64) // 5000
#define R2 474                // 2*NREL
#define FIN 128
#define FOUT 128
#define CSTR 132              // padded smem row stride (132*4B = 528B, 16B-aligned)

// ---------------- scratch (device globals; no allocation allowed) ----------
__device__ float g_hacc[(size_t)NV * FOUT];            // segment_sum(msg*norm)
__device__ float g_h2[(size_t)NV * FOUT];              // pre-batchnorm activations
__device__ __align__(16) float g_Qin[FIN * FOUT];      // node_rel_w folded with in_w
__device__ __align__(16) float g_Qout[FIN * FOUT];     // node_rel_w folded with out_w
__device__ __align__(16) float g_w1a[FIN * 4];         // node_rel_w folded with att_w[0:32]
__device__ __align__(16) float g_w2a[FIN * 4];         // node_w    folded with att_w[32:64]
__device__ float g_sum[FOUT];                          // batchnorm channel sums
__device__ float g_sumsq[FOUT];                        // batchnorm channel sum of squares

// ---------------- kernel 0: zero scratch -----------------------------------
__global__ void zero_kernel() {
    int idx = blockIdx.x * blockDim.x + threadIdx.x;
    const int n4 = NV * FOUT / 4;
    float4 z = make_float4(0.f, 0.f, 0.f, 0.f);
    for (int i = idx; i < n4; i += gridDim.x * blockDim.x)
        ((float4*)g_hacc)[i] = z;
    if (idx < FOUT) { g_sum[idx] = 0.f; g_sumsq[idx] = 0.f; }
}

// ---------------- kernel 1a: fold attention weights -------------------------
__global__ void wfold_kernel(const float* __restrict__ node_w,
                             const float* __restrict__ node_rel_w,
                             const float* __restrict__ att_w) {
    int i = threadIdx.x;   // 0..127
    if (i >= 128) return;
#pragma unroll
    for (int k = 0; k < 4; k++) {
        float s1 = 0.f, s2 = 0.f;
#pragma unroll
        for (int d = 0; d < 32; d++) {
            s1 = fmaf(node_rel_w[k * 4096 + i * 32 + d], att_w[d], s1);
            s2 = fmaf(node_w[k * 4096 + i * 32 + d], att_w[32 + d], s2);
        }
        g_w1a[i * 4 + k] = s1;
        g_w2a[i * 4 + k] = s2;
    }
}

// ---------------- kernel 1b: fold projection weights -------------------------
__global__ void qfold_kernel(const float* __restrict__ node_rel_w,
                             const float* __restrict__ in_w,
                             const float* __restrict__ out_w) {
    __shared__ float nrw_s[128];  // [k][d] for this feature i
    int i = blockIdx.x;
    int tid = threadIdx.x;
    {
        int k = tid >> 5, d = tid & 31;
        nrw_s[tid] = node_rel_w[k * 4096 + i * 32 + d];
    }
    __syncthreads();

    int k = tid >> 5, o = tid & 31;
    float qi = 0.f, qo = 0.f;
#pragma unroll
    for (int d = 0; d < 32; d++) {
        float w = nrw_s[k * 32 + d];
        qi = fmaf(w, in_w[k * 1024 + d * 32 + o], qi);
        qo = fmaf(w, out_w[k * 1024 + d * 32 + o], qo);
    }
    g_Qin[i * 128 + tid] = qi;
    g_Qout[i * 128 + tid] = qo;
}

// ---------------- kernel 2: fused edge kernel --------------------------------
// smem = Qs(64KB) + comp(33KB) + scale/dst(~1.3KB) = ~100.6KB -> 2 CTAs/SM
__global__ void __launch_bounds__(128, 2) edge_kernel(
    const float* __restrict__ node_repr, const float* __restrict__ rel_repr,
    const int* __restrict__ src, const int* __restrict__ dst,
    const int* __restrict__ etype, const float* __restrict__ nrm) {
    extern __shared__ float sm[];
    float* Qs      = sm;                    // 16384 floats
    float* comp    = Qs + 16384;            // 64*CSTR = 8448
    float* s_scale = comp + 64 * CSTR;      // 256
    int*   s_dst   = (int*)(s_scale + 256); // 64

    int tid = threadIdx.x;
    int tile = blockIdx.x;
    int e0 = tile * 64;
    const float* Q = (tile < HALF_TILES) ? g_Qin : g_Qout;

    // ---- stage Q (64KB, 32 float4 per thread) ----
    {
        const float4* Qg = (const float4*)Q;
        float4* Qs4 = (float4*)Qs;
#pragma unroll
        for (int q = 0; q < 32; q++) Qs4[tid + q * 128] = Qg[tid + q * 128];
    }

    // ---- per-pair edge indices (2 threads per edge, direct LDG) ----
    int e = tid >> 1;
    int h = tid & 1;
    int ioff = h * 64;
    int isrc = __ldg(src + e0 + e);
    int idst = __ldg(dst + e0 + e);
    int iet  = __ldg(etype + e0 + e);
    float nv = __ldg(nrm + e0 + e);
    if (h == 0) s_dst[e] = idst;

    // ---- gather + compose + inline attention logits ----
    {
        const float4* xs = (const float4*)(node_repr + (size_t)isrc * 128 + ioff);
        const float4* rr = (const float4*)(rel_repr  + (size_t)iet  * 128 + ioff);
        const float4* xd = (const float4*)(node_repr + (size_t)idst * 128 + ioff);
        const float4* w1 = ((const float4*)g_w1a) + ioff;  // row i -> 4 k-values
        const float4* w2 = ((const float4*)g_w2a) + ioff;
        float* cp = comp + e * CSTR + ioff;
        float lg0 = 0.f, lg1 = 0.f, lg2 = 0.f, lg3 = 0.f;
#pragma unroll
        for (int q = 0; q < 16; q++) {
            float4 a = xs[q], r4 = rr[q], dv = xd[q];
            float4 c;
            c.x = a.x * r4.x; c.y = a.y * r4.y; c.z = a.z * r4.z; c.w = a.w * r4.w;
            *(float4*)(cp + q * 4) = c;
            int ib = q * 4;
            float4 wv;
            wv = w1[ib + 0]; lg0 = fmaf(c.x, wv.x, lg0); lg1 = fmaf(c.x, wv.y, lg1); lg2 = fmaf(c.x, wv.z, lg2); lg3 = fmaf(c.x, wv.w, lg3);
            wv = w1[ib + 1]; lg0 = fmaf(c.y, wv.x, lg0); lg1 = fmaf(c.y, wv.y, lg1); lg2 = fmaf(c.y, wv.z, lg2); lg3 = fmaf(c.y, wv.w, lg3);
            wv = w1[ib + 2]; lg0 = fmaf(c.z, wv.x, lg0); lg1 = fmaf(c.z, wv.y, lg1); lg2 = fmaf(c.z, wv.z, lg2); lg3 = fmaf(c.z, wv.w, lg3);
            wv = w1[ib + 3]; lg0 = fmaf(c.w, wv.x, lg0); lg1 = fmaf(c.w, wv.y, lg1); lg2 = fmaf(c.w, wv.z, lg2); lg3 = fmaf(c.w, wv.w, lg3);
            wv = w2[ib + 0]; lg0 = fmaf(dv.x, wv.x, lg0); lg1 = fmaf(dv.x, wv.y, lg1); lg2 = fmaf(dv.x, wv.z, lg2); lg3 = fmaf(dv.x, wv.w, lg3);
            wv = w2[ib + 1]; lg0 = fmaf(dv.y, wv.x, lg0); lg1 = fmaf(dv.y, wv.y, lg1); lg2 = fmaf(dv.y, wv.z, lg2); lg3 = fmaf(dv.y, wv.w, lg3);
            wv = w2[ib + 2]; lg0 = fmaf(dv.z, wv.x, lg0); lg1 = fmaf(dv.z, wv.y, lg1); lg2 = fmaf(dv.z, wv.z, lg2); lg3 = fmaf(dv.z, wv.w, lg3);
            wv = w2[ib + 3]; lg0 = fmaf(dv.w, wv.x, lg0); lg1 = fmaf(dv.w, wv.y, lg1); lg2 = fmaf(dv.w, wv.z, lg2); lg3 = fmaf(dv.w, wv.w, lg3);
        }
        // combine the two half-feature partials (lanes h=0/h=1)
        lg0 += __shfl_xor_sync(0xFFFFFFFFu, lg0, 1);
        lg1 += __shfl_xor_sync(0xFFFFFFFFu, lg1, 1);
        lg2 += __shfl_xor_sync(0xFFFFFFFFu, lg2, 1);
        lg3 += __shfl_xor_sync(0xFFFFFFFFu, lg3, 1);
        if (h == 0) {
            float l0 = fmaxf(lg0, 0.f);
            float l1 = fmaxf(lg1, 0.f);
            float l2 = fmaxf(lg2, 0.f);
            float l3 = fmaxf(lg3, 0.f);
            float e0x = expf(l0), e1x = expf(l1), e2x = expf(l2), e3x = expf(l3);
            float inv = nv / (e0x + e1x + e2x + e3x);   // /3 applied in node kernel
            s_scale[e * 4 + 0] = e0x * inv;
            s_scale[e * 4 + 1] = e1x * inv;
            s_scale[e * 4 + 2] = e2x * inv;
            s_scale[e * 4 + 3] = e3x * inv;
        }
    }
    __syncthreads();

    // ---- GEMM 64x128x128: thread tile = 8 rows x 8 CONTIGUOUS cols ----
    int c4 = tid & 15;   // column group: cols c4*8 .. c4*8+7
    int r  = tid >> 4;   // row group:    rows r*8 .. r*8+7
    float acc[8][8];
#pragma unroll
    for (int u = 0; u < 8; u++)
#pragma unroll
        for (int j = 0; j < 8; j++) acc[u][j] = 0.f;

    const float* ap = comp + (r * 8) * CSTR;
    const float* bbase = Qs + c4 * 8;
#pragma unroll 1
    for (int k = 0; k < 128; k += 4) {
        float b[4][8];
#pragma unroll
        for (int kk = 0; kk < 4; kk++) {
            const float4* row = (const float4*)(bbase + (k + kk) * 128);
            float4 t0 = row[0], t1 = row[1];
            b[kk][0] = t0.x; b[kk][1] = t0.y; b[kk][2] = t0.z; b[kk][3] = t0.w;
            b[kk][4] = t1.x; b[kk][5] = t1.y; b[kk][6] = t1.z; b[kk][7] = t1.w;
        }
#pragma unroll
        for (int u = 0; u < 8; u++) {
            float4 a4 = *(const float4*)(ap + u * CSTR + k);
            float av[4] = {a4.x, a4.y, a4.z, a4.w};
#pragma unroll
            for (int kk = 0; kk < 4; kk++)
#pragma unroll
                for (int j = 0; j < 8; j++)
                    acc[u][j] = fmaf(av[kk], b[kk][j], acc[u][j]);
        }
    }

    // ---- scatter: hacc[dst] += scale[e, k(c)] * acc; one k-factor per thread ----
    int kfac = c4 >> 2;  // (c4*8)/32
#pragma unroll
    for (int u = 0; u < 8; u++) {
        int ee = r * 8 + u;
        float scv = s_scale[ee * 4 + kfac];
        float* hp = g_hacc + (size_t)s_dst[ee] * 128 + c4 * 8;
#pragma unroll
        for (int j = 0; j < 8; j++)
            atomicAdd(hp + j, acc[u][j] * scv);
    }
}

// ---------------- kernel 3: node kernel (self-loop GEMM + fused BN stats) ---
// h = hacc/3;  g_h2 = h + (h*loop_rel)@loop_w/3 + bias; accumulate sum/sumsq
__global__ void __launch_bounds__(128) node_kernel(
    const float* __restrict__ loop_rel, const float* __restrict__ loop_w,
    const float* __restrict__ bias) {
    extern __shared__ float sm[];
    float* Ws     = sm;                 // 16384
    float* t      = Ws + 16384;         // 64*CSTR
    float* sh     = t + 64 * CSTR;      // 64*CSTR
    float* colsum = sh + 64 * CSTR;     // 128
    float* colsq  = colsum + 128;       // 128

    int tid = threadIdx.x;
    int row0 = blockIdx.x * 64;

    {
        const float4* Wg = (const float4*)loop_w;
        float4* Ws4 = (float4*)Ws;
#pragma unroll
        for (int q = 0; q < 32; q++) Ws4[tid + q * 128] = Wg[tid + q * 128];
    }
    if (tid < 128) { colsum[tid] = 0.f; colsq[tid] = 0.f; }

    // stage h = hacc/3 and t = h * loop_rel
    {
        int e = tid >> 1;
        int ioff = (tid & 1) * 64;
        int row = row0 + e;
        float* tp = t + e * CSTR + ioff;
        float* hp = sh + e * CSTR + ioff;
        if (row < NV) {
            const float4* hv4 = (const float4*)(g_hacc + (size_t)row * 128 + ioff);
            const float4* lr4 = (const float4*)(loop_rel + ioff);
#pragma unroll
            for (int q = 0; q < 16; q++) {
                float4 hh = hv4[q];
                hh.x *= (1.f / 3.f); hh.y *= (1.f / 3.f); hh.z *= (1.f / 3.f); hh.w *= (1.f / 3.f);
                *(float4*)(hp + q * 4) = hh;
                float4 lr = lr4[q];
                float4 tv;
                tv.x = hh.x * lr.x; tv.y = hh.y * lr.y; tv.z = hh.z * lr.z; tv.w = hh.w * lr.w;
                *(float4*)(tp + q * 4) = tv;
            }
        } else {
            float4 z = make_float4(0.f, 0.f, 0.f, 0.f);
#pragma unroll
            for (int q = 0; q < 16; q++) {
                *(float4*)(hp + q * 4) = z;
                *(float4*)(tp + q * 4) = z;
            }
        }
    }
    __syncthreads();

    int c4 = tid & 15, r = tid >> 4;
    float acc[8][8];
#pragma unroll
    for (int u = 0; u < 8; u++)
#pragma unroll
        for (int j = 0; j < 8; j++) acc[u][j] = 0.f;

    const float* ap = t + (r * 8) * CSTR;
    const float* bbase = Ws + c4 * 8;
#pragma unroll 1
    for (int k = 0; k < 128; k += 4) {
        float b[4][8];
#pragma unroll
        for (int kk = 0; kk < 4; kk++) {
            const float4* row = (const float4*)(bbase + (k + kk) * 128);
            float4 t0 = row[0], t1 = row[1];
            b[kk][0] = t0.x; b[kk][1] = t0.y; b[kk][2] = t0.z; b[kk][3] = t0.w;
            b[kk][4] = t1.x; b[kk][5] = t1.y; b[kk][6] = t1.z; b[kk][7] = t1.w;
        }
#pragma unroll
        for (int u = 0; u < 8; u++) {
            float4 a4 = *(const float4*)(ap + u * CSTR + k);
            float av[4] = {a4.x, a4.y, a4.z, a4.w};
#pragma unroll
            for (int kk = 0; kk < 4; kk++)
#pragma unroll
                for (int j = 0; j < 8; j++)
                    acc[u][j] = fmaf(av[kk], b[kk][j], acc[u][j]);
        }
    }

    float psum[8], psq[8];
#pragma unroll
    for (int j = 0; j < 8; j++) { psum[j] = 0.f; psq[j] = 0.f; }
#pragma unroll
    for (int u = 0; u < 8; u++) {
        int e = r * 8 + u;
        int row = row0 + e;
        if (row < NV) {
#pragma unroll
            for (int j = 0; j < 8; j++) {
                int col = c4 * 8 + j;
                float v = sh[e * CSTR + col] + acc[u][j] * (1.f / 3.f) + bias[col];
                g_h2[(size_t)row * 128 + col] = v;
                psum[j] += v;
                psq[j] = fmaf(v, v, psq[j]);
            }
        }
    }
#pragma unroll
    for (int j = 0; j < 8; j++) {
        int col = c4 * 8 + j;
        atomicAdd(&colsum[col], psum[j]);
        atomicAdd(&colsq[col], psq[j]);
    }
    __syncthreads();
    if (tid < 128) {
        atomicAdd(&g_sum[tid], colsum[tid]);
        atomicAdd(&g_sumsq[tid], colsq[tid]);
    }
}

// ---------------- kernel 4: batchnorm + tanh ---------------------------------
__global__ void finalize_kernel(const float* __restrict__ gamma,
                                const float* __restrict__ beta,
                                float* __restrict__ out) {
    __shared__ float sa[128], sb[128];
    int tid = threadIdx.x;
    if (tid < 128) {
        float mean = g_sum[tid] * (1.f / NV);
        float var = g_sumsq[tid] * (1.f / NV) - mean * mean;
        float a = gamma[tid] * rsqrtf(var + 1e-5f);
        sa[tid] = a;
        sb[tid] = beta[tid] - mean * a;
    }
    __syncthreads();
    const int n4 = NV * FOUT / 4;
    for (int i = blockIdx.x * blockDim.x + tid; i < n4; i += gridDim.x * blockDim.x) {
        float4 v = ((const float4*)g_h2)[i];
        int c0 = (i * 4) & 127;
        float4 y;
        y.x = tanhf(fmaf(v.x, sa[c0 + 0], sb[c0 + 0]));
        y.y = tanhf(fmaf(v.y, sa[c0 + 1], sb[c0 + 1]));
        y.z = tanhf(fmaf(v.z, sa[c0 + 2], sb[c0 + 2]));
        y.w = tanhf(fmaf(v.w, sa[c0 + 3], sb[c0 + 3]));
        ((float4*)out)[i] = y;
    }
}

// ---------------- kernel 5: rel_out = rel_repr @ w_rel -----------------------
__global__ void relout_kernel(const float* __restrict__ rel_repr,
                              const float* __restrict__ w_rel,
                              float* __restrict__ out) {
    __shared__ float rrow[128];
    int b = blockIdx.x, tid = threadIdx.x;
    rrow[tid] = rel_repr[b * 128 + tid];
    __syncthreads();
    float s = 0.f;
#pragma unroll 4
    for (int i = 0; i < 128; i++) s = fmaf(rrow[i], w_rel[i * 128 + tid], s);
    out[(size_t)NV * FOUT + b * 128 + tid] = s;
}

// ---------------- host launcher ----------------------------------------------
extern "C" void kernel_launch(void* const* d_in, const int* in_sizes, int n_in,
                              void* d_out, int out_size) {
    const float* node_repr  = (const float*)d_in[0];
    const float* rel_repr   = (const float*)d_in[1];
    const int*   src        = (const int*)d_in[2];
    const int*   dst        = (const int*)d_in[3];
    const int*   etype      = (const int*)d_in[4];
    const float* nrm        = (const float*)d_in[5];
    const float* node_w     = (const float*)d_in[6];
    const float* node_rel_w = (const float*)d_in[7];
    const float* in_w       = (const float*)d_in[8];
    const float* out_w      = (const float*)d_in[9];
    const float* att_w      = (const float*)d_in[10];
    const float* loop_rel   = (const float*)d_in[11];
    const float* loop_w     = (const float*)d_in[12];
    const float* w_rel      = (const float*)d_in[13];
    const float* bias       = (const float*)d_in[14];
    const float* bn_gamma   = (const float*)d_in[15];
    const float* bn_beta    = (const float*)d_in[16];
    float* out = (float*)d_out;

    static const int EDGE_SMEM = (16384 + 64 * CSTR + 256 + 64) * 4;        // ~100.6 KB
    static const int NODE_SMEM = (16384 + 2 * 64 * CSTR + 256) * 4;         // ~134 KB
    cudaFuncSetAttribute(edge_kernel, cudaFuncAttributeMaxDynamicSharedMemorySize, EDGE_SMEM);
    cudaFuncSetAttribute(node_kernel, cudaFuncAttributeMaxDynamicSharedMemorySize, NODE_SMEM);

    zero_kernel<<<512, 256>>>();
    wfold_kernel<<<1, 128>>>(node_w, node_rel_w, att_w);
    qfold_kernel<<<128, 128>>>(node_rel_w, in_w, out_w);
    edge_kernel<<<NTILES, 128, EDGE_SMEM>>>(node_repr, rel_repr, src, dst, etype, nrm);
    node_kernel<<<(NV + 63) / 64, 128, NODE_SMEM>>>(loop_rel, loop_w, bias);
    finalize_kernel<<<1024, 256>>>(bn_gamma, bn_beta, out);
    relout_kernel<<<R2, 128>>>(rel_repr, w_rel, out);
}

// round 6
// speedup vs baseline: 1.3654x; 1.3654x over previous
#include <cuda_runtime.h>
#include <math.h>

// Problem constants
#define NV 50000
#define NE 640000
#define NHALF 320000
#define NTILES (NE/64)        // 10000
#define HALF_TILES (NHALF/64) // 5000
#define GRID_HALF 148         // persistent CTAs per half (1 per SM)
#define R2 474                // 2*NREL
#define FIN 128
#define FOUT 128
#define CSTR 132              // padded smem row stride

// ---------------- scratch (device globals; no allocation allowed) ----------
__device__ float g_hacc[(size_t)NV * FOUT];            // segment_sum(msg*norm)
__device__ float g_h2[(size_t)NV * FOUT];              // pre-batchnorm activations
__device__ __align__(16) float g_Qin[FIN * FOUT];      // node_rel_w folded with in_w
__device__ __align__(16) float g_Qout[FIN * FOUT];     // node_rel_w folded with out_w
__device__ __align__(16) float g_w1a[FIN * 4];         // node_rel_w folded with att_w[0:32]
__device__ __align__(16) float g_w2a[FIN * 4];         // node_w    folded with att_w[32:64]
__device__ float g_sum[FOUT];                          // batchnorm channel sums
__device__ float g_sumsq[FOUT];                        // batchnorm channel sum of squares

// ---------------- kernel 0: zero scratch -----------------------------------
__global__ void zero_kernel() {
    int idx = blockIdx.x * blockDim.x + threadIdx.x;
    const int n4 = NV * FOUT / 4;
    float4 z = make_float4(0.f, 0.f, 0.f, 0.f);
    for (int i = idx; i < n4; i += gridDim.x * blockDim.x)
        ((float4*)g_hacc)[i] = z;
    if (idx < FOUT) { g_sum[idx] = 0.f; g_sumsq[idx] = 0.f; }
}

// ---------------- kernel 1a: fold attention weights -------------------------
__global__ void wfold_kernel(const float* __restrict__ node_w,
                             const float* __restrict__ node_rel_w,
                             const float* __restrict__ att_w) {
    int i = threadIdx.x;   // 0..127
    if (i >= 128) return;
#pragma unroll
    for (int k = 0; k < 4; k++) {
        float s1 = 0.f, s2 = 0.f;
#pragma unroll
        for (int d = 0; d < 32; d++) {
            s1 = fmaf(node_rel_w[k * 4096 + i * 32 + d], att_w[d], s1);
            s2 = fmaf(node_w[k * 4096 + i * 32 + d], att_w[32 + d], s2);
        }
        g_w1a[i * 4 + k] = s1;
        g_w2a[i * 4 + k] = s2;
    }
}

// ---------------- kernel 1b: fold projection weights -------------------------
__global__ void qfold_kernel(const float* __restrict__ node_rel_w,
                             const float* __restrict__ in_w,
                             const float* __restrict__ out_w) {
    __shared__ float nrw_s[128];  // [k][d] for this feature i
    int i = blockIdx.x;
    int tid = threadIdx.x;
    {
        int k = tid >> 5, d = tid & 31;
        nrw_s[tid] = node_rel_w[k * 4096 + i * 32 + d];
    }
    __syncthreads();

    int k = tid >> 5, o = tid & 31;
    float qi = 0.f, qo = 0.f;
#pragma unroll
    for (int d = 0; d < 32; d++) {
        float w = nrw_s[k * 32 + d];
        qi = fmaf(w, in_w[k * 1024 + d * 32 + o], qi);
        qo = fmaf(w, out_w[k * 1024 + d * 32 + o], qo);
    }
    g_Qin[i * 128 + tid] = qi;
    g_Qout[i * 128 + tid] = qo;
}

// ---------------- kernel 2: fused edge kernel (persistent CTAs) --------------
// Grid = 2*GRID_HALF. CTA < GRID_HALF handles Qin tiles; rest handle Qout.
// Q staged ONCE per CTA; loop over tiles: gather+logits -> GEMM -> red.v4 scatter.
// smem ~100.6 KB -> 2 CTAs/SM (one of each half per SM).
__global__ void __launch_bounds__(128, 2) edge_kernel(
    const float* __restrict__ node_repr, const float* __restrict__ rel_repr,
    const int* __restrict__ src, const int* __restrict__ dst,
    const int* __restrict__ etype, const float* __restrict__ nrm) {
    extern __shared__ float sm[];
    float* Qs      = sm;                    // 16384 floats
    float* comp    = Qs + 16384;            // 64*CSTR = 8448
    float* s_scale = comp + 64 * CSTR;      // 256
    int*   s_dst   = (int*)(s_scale + 256); // 64

    int tid = threadIdx.x;
    int cta = blockIdx.x;
    int halfsel = (cta >= GRID_HALF) ? 1 : 0;
    int tile0 = cta - halfsel * GRID_HALF;
    const float* Q = halfsel ? g_Qout : g_Qin;

    // ---- stage Q once (64KB, 32 float4 per thread) ----
    {
        const float4* Qg = (const float4*)Q;
        float4* Qs4 = (float4*)Qs;
#pragma unroll
        for (int q = 0; q < 32; q++) Qs4[tid + q * 128] = Qg[tid + q * 128];
    }

    int e = tid >> 1;        // edge within tile (2 threads per edge)
    int h = tid & 1;
    int ioff = h * 64;
    int c4 = tid & 15;       // column quad group
    int r  = tid >> 4;       // row group (8 rows)
    int kf0 = c4 >> 3;       // k-factor of quad0 (cols c4*4..+3): 0 or 1

    for (int tile = tile0; tile < HALF_TILES; tile += GRID_HALF) {
        int e0 = (tile + halfsel * HALF_TILES) * 64;
        __syncthreads();  // protect comp/s_scale/s_dst from prior iteration's readers

        // ---- gather + compose + inline attention logits ----
        int isrc = __ldg(src + e0 + e);
        int idst = __ldg(dst + e0 + e);
        int iet  = __ldg(etype + e0 + e);
        float nv = __ldg(nrm + e0 + e);
        if (h == 0) s_dst[e] = idst;
        {
            const float4* xs = (const float4*)(node_repr + (size_t)isrc * 128 + ioff);
            const float4* rr = (const float4*)(rel_repr  + (size_t)iet  * 128 + ioff);
            const float4* xd = (const float4*)(node_repr + (size_t)idst * 128 + ioff);
            const float4* w1 = ((const float4*)g_w1a) + ioff;  // row i -> 4 k-values
            const float4* w2 = ((const float4*)g_w2a) + ioff;
            float* cp = comp + e * CSTR + ioff;
            float lg0 = 0.f, lg1 = 0.f, lg2 = 0.f, lg3 = 0.f;
#pragma unroll 4
            for (int q = 0; q < 16; q++) {
                float4 a = xs[q], r4 = rr[q], dv = xd[q];
                float4 c;
                c.x = a.x * r4.x; c.y = a.y * r4.y; c.z = a.z * r4.z; c.w = a.w * r4.w;
                *(float4*)(cp + q * 4) = c;
                int ib = q * 4;
                float4 wv;
                wv = w1[ib + 0]; lg0 = fmaf(c.x, wv.x, lg0); lg1 = fmaf(c.x, wv.y, lg1); lg2 = fmaf(c.x, wv.z, lg2); lg3 = fmaf(c.x, wv.w, lg3);
                wv = w1[ib + 1]; lg0 = fmaf(c.y, wv.x, lg0); lg1 = fmaf(c.y, wv.y, lg1); lg2 = fmaf(c.y, wv.z, lg2); lg3 = fmaf(c.y, wv.w, lg3);
                wv = w1[ib + 2]; lg0 = fmaf(c.z, wv.x, lg0); lg1 = fmaf(c.z, wv.y, lg1); lg2 = fmaf(c.z, wv.z, lg2); lg3 = fmaf(c.z, wv.w, lg3);
                wv = w1[ib + 3]; lg0 = fmaf(c.w, wv.x, lg0); lg1 = fmaf(c.w, wv.y, lg1); lg2 = fmaf(c.w, wv.z, lg2); lg3 = fmaf(c.w, wv.w, lg3);
                wv = w2[ib + 0]; lg0 = fmaf(dv.x, wv.x, lg0); lg1 = fmaf(dv.x, wv.y, lg1); lg2 = fmaf(dv.x, wv.z, lg2); lg3 = fmaf(dv.x, wv.w, lg3);
                wv = w2[ib + 1]; lg0 = fmaf(dv.y, wv.x, lg0); lg1 = fmaf(dv.y, wv.y, lg1); lg2 = fmaf(dv.y, wv.z, lg2); lg3 = fmaf(dv.y, wv.w, lg3);
                wv = w2[ib + 2]; lg0 = fmaf(dv.z, wv.x, lg0); lg1 = fmaf(dv.z, wv.y, lg1); lg2 = fmaf(dv.z, wv.z, lg2); lg3 = fmaf(dv.z, wv.w, lg3);
                wv = w2[ib + 3]; lg0 = fmaf(dv.w, wv.x, lg0); lg1 = fmaf(dv.w, wv.y, lg1); lg2 = fmaf(dv.w, wv.z, lg2); lg3 = fmaf(dv.w, wv.w, lg3);
            }
            // combine the two half-feature partials (lanes h=0/h=1)
            lg0 += __shfl_xor_sync(0xFFFFFFFFu, lg0, 1);
            lg1 += __shfl_xor_sync(0xFFFFFFFFu, lg1, 1);
            lg2 += __shfl_xor_sync(0xFFFFFFFFu, lg2, 1);
            lg3 += __shfl_xor_sync(0xFFFFFFFFu, lg3, 1);
            if (h == 0) {
                float l0 = fmaxf(lg0, 0.f);
                float l1 = fmaxf(lg1, 0.f);
                float l2 = fmaxf(lg2, 0.f);
                float l3 = fmaxf(lg3, 0.f);
                float e0x = expf(l0), e1x = expf(l1), e2x = expf(l2), e3x = expf(l3);
                float inv = nv / (e0x + e1x + e2x + e3x);   // /3 applied in node kernel
                s_scale[e * 4 + 0] = e0x * inv;
                s_scale[e * 4 + 1] = e1x * inv;
                s_scale[e * 4 + 2] = e2x * inv;
                s_scale[e * 4 + 3] = e3x * inv;
            }
        }
        __syncthreads();

        // ---- GEMM 64x128x128 (round-3 scalar form, regs ~126) ----
        // thread tile: rows r*8..r*8+7, cols quad0 = c4*4..+3, quad1 = 64+c4*4..+3
        float acc[8][8];
#pragma unroll
        for (int u = 0; u < 8; u++)
#pragma unroll
            for (int m = 0; m < 8; m++) acc[u][m] = 0.f;

        const float* ap = comp + (r * 8) * CSTR;
        const float* bp = Qs + c4 * 4;
#pragma unroll 1
        for (int k = 0; k < 128; k += 4) {
#pragma unroll
            for (int kk = 0; kk < 4; kk++) {
                const float* brow = bp + (k + kk) * 128;
                float bv[8];
#pragma unroll
                for (int m = 0; m < 4; m++) bv[m] = brow[m];
#pragma unroll
                for (int m = 0; m < 4; m++) bv[4 + m] = brow[64 + m];
#pragma unroll
                for (int u = 0; u < 8; u++) {
                    float av = ap[u * CSTR + k + kk];
#pragma unroll
                    for (int m = 0; m < 8; m++) acc[u][m] = fmaf(av, bv[m], acc[u][m]);
                }
            }
        }

        // ---- scatter: vectorized red.global.add.v4 per quad ----
#pragma unroll
        for (int u = 0; u < 8; u++) {
            int ee = r * 8 + u;
            float s0 = s_scale[ee * 4 + kf0];
            float s1 = s_scale[ee * 4 + 2 + kf0];
            float* hp = g_hacc + (size_t)s_dst[ee] * 128 + c4 * 4;
            asm volatile("red.global.add.v4.f32 [%0], {%1, %2, %3, %4};"
                :: "l"(hp),
                   "f"(acc[u][0] * s0), "f"(acc[u][1] * s0),
                   "f"(acc[u][2] * s0), "f"(acc[u][3] * s0)
                : "memory");
            asm volatile("red.global.add.v4.f32 [%0], {%1, %2, %3, %4};"
                :: "l"(hp + 64),
                   "f"(acc[u][4] * s1), "f"(acc[u][5] * s1),
                   "f"(acc[u][6] * s1), "f"(acc[u][7] * s1)
                : "memory");
        }
    }
}

// ---------------- kernel 3: node kernel (self-loop GEMM + fused BN stats) ---
// h = hacc/3;  g_h2 = h + (h*loop_rel)@loop_w/3 + bias; accumulate sum/sumsq
__global__ void __launch_bounds__(128) node_kernel(
    const float* __restrict__ loop_rel, const float* __restrict__ loop_w,
    const float* __restrict__ bias) {
    extern __shared__ float sm[];
    float* Ws     = sm;                 // 16384
    float* t      = Ws + 16384;         // 64*CSTR
    float* sh     = t + 64 * CSTR;      // 64*CSTR
    float* colsum = sh + 64 * CSTR;     // 128
    float* colsq  = colsum + 128;       // 128

    int tid = threadIdx.x;
    int row0 = blockIdx.x * 64;

    {
        const float4* Wg = (const float4*)loop_w;
        float4* Ws4 = (float4*)Ws;
#pragma unroll
        for (int q = 0; q < 32; q++) Ws4[tid + q * 128] = Wg[tid + q * 128];
    }
    if (tid < 128) { colsum[tid] = 0.f; colsq[tid] = 0.f; }

    // stage h = hacc/3 and t = h * loop_rel
    {
        int e = tid >> 1;
        int ioff = (tid & 1) * 64;
        int row = row0 + e;
        float* tp = t + e * CSTR + ioff;
        float* hp = sh + e * CSTR + ioff;
        if (row < NV) {
            const float4* hv4 = (const float4*)(g_hacc + (size_t)row * 128 + ioff);
            const float4* lr4 = (const float4*)(loop_rel + ioff);
#pragma unroll
            for (int q = 0; q < 16; q++) {
                float4 hh = hv4[q];
                hh.x *= (1.f / 3.f); hh.y *= (1.f / 3.f); hh.z *= (1.f / 3.f); hh.w *= (1.f / 3.f);
                *(float4*)(hp + q * 4) = hh;
                float4 lr = lr4[q];
                float4 tv;
                tv.x = hh.x * lr.x; tv.y = hh.y * lr.y; tv.z = hh.z * lr.z; tv.w = hh.w * lr.w;
                *(float4*)(tp + q * 4) = tv;
            }
        } else {
            float4 z = make_float4(0.f, 0.f, 0.f, 0.f);
#pragma unroll
            for (int q = 0; q < 16; q++) {
                *(float4*)(hp + q * 4) = z;
                *(float4*)(tp + q * 4) = z;
            }
        }
    }
    __syncthreads();

    int c4 = tid & 15, r = tid >> 4;
    float acc[8][8];
#pragma unroll
    for (int u = 0; u < 8; u++)
#pragma unroll
        for (int m = 0; m < 8; m++) acc[u][m] = 0.f;

    const float* ap = t + (r * 8) * CSTR;
    const float* bp = Ws + c4 * 4;
#pragma unroll 1
    for (int k = 0; k < 128; k += 4) {
#pragma unroll
        for (int kk = 0; kk < 4; kk++) {
            const float* brow = bp + (k + kk) * 128;
            float bv[8];
#pragma unroll
            for (int m = 0; m < 4; m++) bv[m] = brow[m];
#pragma unroll
            for (int m = 0; m < 4; m++) bv[4 + m] = brow[64 + m];
#pragma unroll
            for (int u = 0; u < 8; u++) {
                float av = ap[u * CSTR + k + kk];
#pragma unroll
                for (int m = 0; m < 8; m++) acc[u][m] = fmaf(av, bv[m], acc[u][m]);
            }
        }
    }

    float psum[8], psq[8];
#pragma unroll
    for (int m = 0; m < 8; m++) { psum[m] = 0.f; psq[m] = 0.f; }
#pragma unroll
    for (int u = 0; u < 8; u++) {
        int e = r * 8 + u;
        int row = row0 + e;
        if (row < NV) {
#pragma unroll
            for (int m = 0; m < 8; m++) {
                int col = (m < 4) ? (c4 * 4 + m) : (64 + c4 * 4 + m - 4);
                float v = sh[e * CSTR + col] + acc[u][m] * (1.f / 3.f) + bias[col];
                g_h2[(size_t)row * 128 + col] = v;
                psum[m] += v;
                psq[m] = fmaf(v, v, psq[m]);
            }
        }
    }
#pragma unroll
    for (int m = 0; m < 8; m++) {
        int col = (m < 4) ? (c4 * 4 + m) : (64 + c4 * 4 + m - 4);
        atomicAdd(&colsum[col], psum[m]);
        atomicAdd(&colsq[col], psq[m]);
    }
    __syncthreads();
    if (tid < 128) {
        atomicAdd(&g_sum[tid], colsum[tid]);
        atomicAdd(&g_sumsq[tid], colsq[tid]);
    }
}

// ---------------- kernel 4: batchnorm + tanh ---------------------------------
__global__ void finalize_kernel(const float* __restrict__ gamma,
                                const float* __restrict__ beta,
                                float* __restrict__ out) {
    __shared__ float sa[128], sb[128];
    int tid = threadIdx.x;
    if (tid < 128) {
        float mean = g_sum[tid] * (1.f / NV);
        float var = g_sumsq[tid] * (1.f / NV) - mean * mean;
        float a = gamma[tid] * rsqrtf(var + 1e-5f);
        sa[tid] = a;
        sb[tid] = beta[tid] - mean * a;
    }
    __syncthreads();
    const int n4 = NV * FOUT / 4;
    for (int i = blockIdx.x * blockDim.x + tid; i < n4; i += gridDim.x * blockDim.x) {
        float4 v = ((const float4*)g_h2)[i];
        int c0 = (i * 4) & 127;
        float4 y;
        y.x = tanhf(fmaf(v.x, sa[c0 + 0], sb[c0 + 0]));
        y.y = tanhf(fmaf(v.y, sa[c0 + 1], sb[c0 + 1]));
        y.z = tanhf(fmaf(v.z, sa[c0 + 2], sb[c0 + 2]));
        y.w = tanhf(fmaf(v.w, sa[c0 + 3], sb[c0 + 3]));
        ((float4*)out)[i] = y;
    }
}

// ---------------- kernel 5: rel_out = rel_repr @ w_rel -----------------------
__global__ void relout_kernel(const float* __restrict__ rel_repr,
                              const float* __restrict__ w_rel,
                              float* __restrict__ out) {
    __shared__ float rrow[128];
    int b = blockIdx.x, tid = threadIdx.x;
    rrow[tid] = rel_repr[b * 128 + tid];
    __syncthreads();
    float s = 0.f;
#pragma unroll 4
    for (int i = 0; i < 128; i++) s = fmaf(rrow[i], w_rel[i * 128 + tid], s);
    out[(size_t)NV * FOUT + b * 128 + tid] = s;
}

// ---------------- host launcher ----------------------------------------------
extern "C" void kernel_launch(void* const* d_in, const int* in_sizes, int n_in,
                              void* d_out, int out_size) {
    const float* node_repr  = (const float*)d_in[0];
    const float* rel_repr   = (const float*)d_in[1];
    const int*   src        = (const int*)d_in[2];
    const int*   dst        = (const int*)d_in[3];
    const int*   etype      = (const int*)d_in[4];
    const float* nrm        = (const float*)d_in[5];
    const float* node_w     = (const float*)d_in[6];
    const float* node_rel_w = (const float*)d_in[7];
    const float* in_w       = (const float*)d_in[8];
    const float* out_w      = (const float*)d_in[9];
    const float* att_w      = (const float*)d_in[10];
    const float* loop_rel   = (const float*)d_in[11];
    const float* loop_w     = (const float*)d_in[12];
    const float* w_rel      = (const float*)d_in[13];
    const float* bias       = (const float*)d_in[14];
    const float* bn_gamma   = (const float*)d_in[15];
    const float* bn_beta    = (const float*)d_in[16];
    float* out = (float*)d_out;

    static const int EDGE_SMEM = (16384 + 64 * CSTR + 256 + 64) * 4;        // ~100.6 KB
    static const int NODE_SMEM = (16384 + 2 * 64 * CSTR + 256) * 4;         // ~134 KB
    cudaFuncSetAttribute(edge_kernel, cudaFuncAttributeMaxDynamicSharedMemorySize, EDGE_SMEM);
    cudaFuncSetAttribute(node_kernel, cudaFuncAttributeMaxDynamicSharedMemorySize, NODE_SMEM);

    zero_kernel<<<512, 256>>>();
    wfold_kernel<<<1, 128>>>(node_w, node_rel_w, att_w);
    qfold_kernel<<<128, 128>>>(node_rel_w, in_w, out_w);
    edge_kernel<<<2 * GRID_HALF, 128, EDGE_SMEM>>>(node_repr, rel_repr, src, dst, etype, nrm);
    node_kernel<<<(NV + 63) / 64, 128, NODE_SMEM>>>(loop_rel, loop_w, bias);
    finalize_kernel<<<1024, 256>>>(bn_gamma, bn_beta, out);
    relout_kernel<<<R2, 128>>>(rel_repr, w_rel, out);
}